// round 2
// baseline (speedup 1.0000x reference)
#include <cuda_runtime.h>

#define D 128
#define DPAD 132

static __device__ float g_A [46792704];
static __device__ float g_B [46792704];
static __device__ float g_C [46792704];
static __device__ float g_A2[ 2752512];
static __device__ float g_B2[ 2752512];
static __device__ float g_C2[ 2752512];
static __device__ float g_acc [18*256];
static __device__ float g_fold[19*256];
static __device__ float g_wT  [884736];

__global__ void init_kernel(float* acc, float* foldId) {
    int t = blockIdx.x * blockDim.x + threadIdx.x;
    if (t < 18*256) acc[t] = 0.f;
    if (t < 128) { foldId[t] = 1.f; foldId[128 + t] = 0.f; }
}

__global__ void transpose_kernel(const float* __restrict__ src, float* __restrict__ dst,
                                 int R, int C, int total) {
    int idx = blockIdx.x * blockDim.x + threadIdx.x;
    if (idx >= total) return;
    int m  = idx / (R * C);
    int rc = idx - m * (R * C);
    int cc = rc / R;
    int r  = rc - cc * R;
    dst[idx] = src[m * R * C + r * C + cc];
}

__global__ void embed_kernel(const float* __restrict__ poses, const float* __restrict__ ew,
                             const float* __restrict__ eb, float* __restrict__ out, int total) {
    int idx = blockIdx.x * blockDim.x + threadIdx.x;
    if (idx >= total) return;
    int row = idx >> 7, c = idx & 127;
    float v = fmaf(poses[row*2], ew[2*c], fmaf(poses[row*2+1], ew[2*c+1], eb[c]));
    out[idx] = v > 0.f ? v : 0.01f * v;
}

__global__ void finalize_kernel(const float* __restrict__ acc, float invN,
                                const float* g0, const float* b0, float* f0,
                                const float* g1, const float* b1, float* f1) {
    int set = blockIdx.x, c = threadIdx.x;
    const float* a  = acc + set * 256;
    const float* gg = set ? g1 : g0;
    const float* bb = set ? b1 : b0;
    float* ff = set ? f1 : f0;
    float m = a[c] * invN;
    float v = fmaxf(a[128 + c] * invN - m * m, 0.f);
    float sc = rsqrtf(v + 1e-5f) * gg[c];
    ff[c] = sc;
    ff[128 + c] = fmaf(-m, sc, bb[c]);
}

__global__ void pool1_kernel(const float* __restrict__ hin, const float* __restrict__ fold,
                             float* __restrict__ out, int total) {
    int idx = blockIdx.x * blockDim.x + threadIdx.x;
    if (idx >= total) return;
    int orow = idx >> 7, c = idx & 127;
    const float* base = hin + (size_t)orow * 17 * D + c;
    float s = 0.f;
    #pragma unroll
    for (int j = 0; j < 17; ++j) s += base[j * D];
    out[idx] = fmaf(s * (1.f / 17.f), fold[c], fold[128 + c]);
}

__global__ void pool2_cls_kernel(const float* __restrict__ hin, const float* __restrict__ fold,
                                 const float* __restrict__ cw, const float* __restrict__ cb,
                                 float* __restrict__ out) {
    __shared__ float p_s[D];
    int b = blockIdx.x, c = threadIdx.x;
    const float* base = hin + (size_t)b * 84 * D + c;
    float s = 0.f;
    #pragma unroll 4
    for (int r = 0; r < 84; ++r) s += base[r * D];
    p_s[c] = fmaf(s * (1.f / 84.f), fold[c], fold[128 + c]);
    __syncthreads();
    if (c < 8) {
        float acc = cb[c];
        #pragma unroll 4
        for (int k = 0; k < D; ++k) acc = fmaf(p_s[k], cw[c * D + k], acc);
        out[b * 8 + c] = acc;
    }
}

template<int N>
__device__ __forceinline__ void gemm128(const float (*hs)[DPAD], const float* __restrict__ wT,
                                        int ldw, int cidx, float bias, float* out) {
    #pragma unroll
    for (int r = 0; r < N; ++r) out[r] = bias;
    #pragma unroll 2
    for (int k = 0; k < D; k += 4) {
        float w0 = wT[(k + 0) * ldw + cidx];
        float w1 = wT[(k + 1) * ldw + cidx];
        float w2 = wT[(k + 2) * ldw + cidx];
        float w3 = wT[(k + 3) * ldw + cidx];
        #pragma unroll
        for (int r = 0; r < N; ++r) {
            float4 hv = *reinterpret_cast<const float4*>(&hs[r][k]);
            out[r] = fmaf(hv.x, w0, out[r]);
            out[r] = fmaf(hv.y, w1, out[r]);
            out[r] = fmaf(hv.z, w2, out[r]);
            out[r] = fmaf(hv.w, w3, out[r]);
        }
    }
}

template<int N, int GPB>
__global__ __launch_bounds__(128)
void k1_kernel(const float* __restrict__ hin, const float* __restrict__ foldIn,
               float* __restrict__ t1, float* __restrict__ t2, float* __restrict__ acc,
               const float* __restrict__ gwT, const float* __restrict__ gb,
               const float* __restrict__ qwT, const float* __restrict__ qb,
               const float* __restrict__ owT, const float* __restrict__ ob) {
    __shared__ float h_s[N][DPAD];
    __shared__ float q_s[N][DPAD];
    __shared__ float k_s[N][DPAD];
    __shared__ float v_s[N][DPAD];
    __shared__ float sc_s[4][N][N + 1];
    __shared__ float m_s[D];

    const int c = threadIdx.x;
    const int wp = c >> 5, lane = c & 31;
    const float scIn = foldIn[c], shIn = foldIn[D + c];
    const float gbv = gb[c], obv = ob[c];
    const float qbq = qb[c], qbk = qb[D + c], qbv = qb[2 * D + c];
    float s1 = 0.f, sq1 = 0.f, s2 = 0.f, sq2 = 0.f;

    for (int gi = 0; gi < GPB; ++gi) {
        const int g = blockIdx.x * GPB + gi;
        const float* hg = hin + (size_t)g * (N * D);

        float mv = 0.f;
        #pragma unroll
        for (int r = 0; r < N; ++r) {
            float v = fmaf(hg[r * D + c], scIn, shIn);
            h_s[r][c] = v;
            mv += v;
        }
        m_s[c] = mv * (1.f / N);
        __syncthreads();

        float gcnv = gbv;
        #pragma unroll 4
        for (int k = 0; k < D; ++k) gcnv = fmaf(m_s[k], gwT[k * D + c], gcnv);

        {
            float* t1g = t1 + (size_t)g * (N * D);
            #pragma unroll
            for (int r = 0; r < N; ++r) {
                float v = gcnv + h_s[r][c];
                t1g[r * D + c] = v;
                s1 += v; sq1 = fmaf(v, v, sq1);
            }
        }

        {
            float a[N];
            gemm128<N>(h_s, qwT, 384, c,       qbq, a);
            #pragma unroll
            for (int r = 0; r < N; ++r) q_s[r][c] = a[r];
            gemm128<N>(h_s, qwT, 384, c + 128, qbk, a);
            #pragma unroll
            for (int r = 0; r < N; ++r) k_s[r][c] = a[r];
            gemm128<N>(h_s, qwT, 384, c + 256, qbv, a);
            #pragma unroll
            for (int r = 0; r < N; ++r) v_s[r][c] = a[r];
        }
        __syncthreads();

        {
            const float invs = 0.17677669529663687f; // 1/sqrt(32)
            for (int p = lane; p < N * N; p += 32) {
                int r = p / N, s = p - r * N;
                float d0 = 0.f;
                #pragma unroll
                for (int d = 0; d < 32; d += 4) {
                    float4 qq = *reinterpret_cast<const float4*>(&q_s[r][wp * 32 + d]);
                    float4 kk = *reinterpret_cast<const float4*>(&k_s[s][wp * 32 + d]);
                    d0 = fmaf(qq.x, kk.x, d0);
                    d0 = fmaf(qq.y, kk.y, d0);
                    d0 = fmaf(qq.z, kk.z, d0);
                    d0 = fmaf(qq.w, kk.w, d0);
                }
                sc_s[wp][r][s] = d0 * invs;
            }
            __syncwarp();
            if (lane < N) {
                float mx = -1e30f;
                #pragma unroll
                for (int s = 0; s < N; ++s) mx = fmaxf(mx, sc_s[wp][lane][s]);
                float sum = 0.f;
                #pragma unroll
                for (int s = 0; s < N; ++s) {
                    float e = __expf(sc_s[wp][lane][s] - mx);
                    sc_s[wp][lane][s] = e;
                    sum += e;
                }
                float inv = 1.f / sum;
                #pragma unroll
                for (int s = 0; s < N; ++s) sc_s[wp][lane][s] *= inv;
            }
            __syncwarp();
            #pragma unroll
            for (int r = 0; r < N; ++r) {
                float o = 0.f;
                #pragma unroll
                for (int s = 0; s < N; ++s)
                    o = fmaf(sc_s[wp][r][s], v_s[s][wp * 32 + lane], o);
                q_s[r][wp * 32 + lane] = o;  // reuse q_s for attn output
            }
        }
        __syncthreads();

        {
            float a[N];
            gemm128<N>(q_s, owT, 128, c, obv, a);
            float* t2g = t2 + (size_t)g * (N * D);
            #pragma unroll
            for (int r = 0; r < N; ++r) {
                float v = a[r] + h_s[r][c];
                t2g[r * D + c] = v;
                s2 += v; sq2 = fmaf(v, v, sq2);
            }
        }
        __syncthreads();
    }
    atomicAdd(&acc[c],       s1);
    atomicAdd(&acc[128 + c], sq1);
    atomicAdd(&acc[256 + c], s2);
    atomicAdd(&acc[384 + c], sq2);
}

template<int N, int GPB>
__global__ __launch_bounds__(128)
void k2_kernel(const float* __restrict__ t1, const float* __restrict__ t2,
               const float* __restrict__ fold1, const float* __restrict__ fold2,
               float* __restrict__ hout, float* __restrict__ acc,
               const float* __restrict__ w1T, const float* __restrict__ b1,
               const float* __restrict__ w2T, const float* __restrict__ b2) {
    __shared__ float o_s[N][DPAD];
    __shared__ float u_s[N][260];
    const int c = threadIdx.x;
    const float sc1 = fold1[c], sh1 = fold1[128 + c];
    const float sc2 = fold2[c], sh2 = fold2[128 + c];
    const float b1a = b1[c], b1b = b1[128 + c], b2a = b2[c];
    float s3 = 0.f, q3 = 0.f;

    for (int gi = 0; gi < GPB; ++gi) {
        const int g = blockIdx.x * GPB + gi;
        const float* t1g = t1 + (size_t)g * (N * D);
        const float* t2g = t2 + (size_t)g * (N * D);
        #pragma unroll
        for (int r = 0; r < N; ++r)
            o_s[r][c] = fmaf(t1g[r * D + c], sc1, sh1) + fmaf(t2g[r * D + c], sc2, sh2);
        __syncthreads();

        {
            float a0[N], a1[N];
            #pragma unroll
            for (int r = 0; r < N; ++r) { a0[r] = b1a; a1[r] = b1b; }
            #pragma unroll 2
            for (int k = 0; k < D; k += 4) {
                float wa0 = w1T[(k+0)*256 + c], wb0 = w1T[(k+0)*256 + 128 + c];
                float wa1 = w1T[(k+1)*256 + c], wb1 = w1T[(k+1)*256 + 128 + c];
                float wa2 = w1T[(k+2)*256 + c], wb2 = w1T[(k+2)*256 + 128 + c];
                float wa3 = w1T[(k+3)*256 + c], wb3 = w1T[(k+3)*256 + 128 + c];
                #pragma unroll
                for (int r = 0; r < N; ++r) {
                    float4 hv = *reinterpret_cast<const float4*>(&o_s[r][k]);
                    a0[r] = fmaf(hv.x, wa0, a0[r]);  a1[r] = fmaf(hv.x, wb0, a1[r]);
                    a0[r] = fmaf(hv.y, wa1, a0[r]);  a1[r] = fmaf(hv.y, wb1, a1[r]);
                    a0[r] = fmaf(hv.z, wa2, a0[r]);  a1[r] = fmaf(hv.z, wb2, a1[r]);
                    a0[r] = fmaf(hv.w, wa3, a0[r]);  a1[r] = fmaf(hv.w, wb3, a1[r]);
                }
            }
            #pragma unroll
            for (int r = 0; r < N; ++r) {
                u_s[r][c]       = fmaxf(a0[r], 0.f);
                u_s[r][128 + c] = fmaxf(a1[r], 0.f);
            }
        }
        __syncthreads();

        {
            float a0[N];
            #pragma unroll
            for (int r = 0; r < N; ++r) a0[r] = b2a;
            #pragma unroll 2
            for (int j = 0; j < 256; j += 4) {
                float w0  = w2T[(j+0) * D + c];
                float w1v = w2T[(j+1) * D + c];
                float w2v = w2T[(j+2) * D + c];
                float w3  = w2T[(j+3) * D + c];
                #pragma unroll
                for (int r = 0; r < N; ++r) {
                    float4 uv = *reinterpret_cast<const float4*>(&u_s[r][j]);
                    a0[r] = fmaf(uv.x, w0,  a0[r]);
                    a0[r] = fmaf(uv.y, w1v, a0[r]);
                    a0[r] = fmaf(uv.z, w2v, a0[r]);
                    a0[r] = fmaf(uv.w, w3,  a0[r]);
                }
            }
            float* og = hout + (size_t)g * (N * D);
            #pragma unroll
            for (int r = 0; r < N; ++r) {
                float v = o_s[r][c] + a0[r];
                og[r * D + c] = v;
                s3 += v; q3 = fmaf(v, v, q3);
            }
        }
        __syncthreads();
    }
    atomicAdd(&acc[c],       s3);
    atomicAdd(&acc[128 + c], q3);
}

template<int N, int GPB>
static const float* run_gps(const float* const* PP, float* hA, float* hB, float* hC,
                            int G, float invN, const float* wTs, float* acc,
                            float* foldBase, const float* foldId) {
    const float* foldPrev = foldId;
    int blocks = G / GPB;
    for (int l = 0; l < 3; ++l) {
        const float* gwT = wTs + l * 16384;
        const float* qwT = wTs + 49152  + l * 49152;
        const float* owT = wTs + 196608 + l * 16384;
        const float* w1T = wTs + 245760 + l * 32768;
        const float* w2T = wTs + 344064 + l * 32768;
        const float* gb  = PP[1]  + l * 128;
        const float* qb  = PP[3]  + l * 384;
        const float* ob  = PP[5]  + l * 128;
        const float* bng = PP[6]  + l * 384;
        const float* bnb = PP[7]  + l * 384;
        const float* b1  = PP[9]  + l * 256;
        const float* b2  = PP[11] + l * 128;
        float* accL  = acc + l * 768;
        float* foldL = foldBase + l * 768;

        k1_kernel<N, GPB><<<blocks, 128>>>(hA, foldPrev, hB, hC, accL,
                                           gwT, gb, qwT, qb, owT, ob);
        finalize_kernel<<<2, 128>>>(accL, invN, bng, bnb, foldL,
                                    bng + 128, bnb + 128, foldL + 256);
        k2_kernel<N, GPB><<<blocks, 128>>>(hB, hC, foldL, foldL + 256, hA, accL + 512,
                                           w1T, b1, w2T, b2);
        finalize_kernel<<<1, 128>>>(accL + 512, invN, bng + 256, bnb + 256, foldL + 512,
                                    nullptr, nullptr, nullptr);
        foldPrev = foldL + 512;
    }
    return foldPrev;
}

extern "C" void kernel_launch(void* const* d_in, const int* in_sizes, int n_in,
                              void* d_out, int out_size) {
    const float* poses = (const float*)d_in[0];
    const float* emb_w = (const float*)d_in[1];
    const float* emb_b = (const float*)d_in[2];
    const float* cls_w = (const float*)d_in[3];
    const float* cls_b = (const float*)d_in[4];
    const float* PPj[12];
    const float* PPi[12];
    for (int i = 0; i < 12; ++i) {
        PPj[i] = (const float*)d_in[5 + i];
        PPi[i] = (const float*)d_in[17 + i];
    }

    float *A, *Bb, *Cc, *A2, *B2, *C2, *acc, *fold, *wT;
    cudaGetSymbolAddress((void**)&A,    g_A);
    cudaGetSymbolAddress((void**)&Bb,   g_B);
    cudaGetSymbolAddress((void**)&Cc,   g_C);
    cudaGetSymbolAddress((void**)&A2,   g_A2);
    cudaGetSymbolAddress((void**)&B2,   g_B2);
    cudaGetSymbolAddress((void**)&C2,   g_C2);
    cudaGetSymbolAddress((void**)&acc,  g_acc);
    cudaGetSymbolAddress((void**)&fold, g_fold);
    cudaGetSymbolAddress((void**)&wT,   g_wT);
    const float* foldId = fold + 18 * 256;

    init_kernel<<<18, 256>>>(acc, fold + 18 * 256);

    for (int s = 0; s < 2; ++s) {
        const float* const* PP = s ? PPi : PPj;
        float* wTs = wT + s * 442368;
        transpose_kernel<<<192, 256>>>(PP[0],  wTs + 0,      128, 128, 49152);
        transpose_kernel<<<576, 256>>>(PP[2],  wTs + 49152,  384, 128, 147456);
        transpose_kernel<<<192, 256>>>(PP[4],  wTs + 196608, 128, 128, 49152);
        transpose_kernel<<<384, 256>>>(PP[8],  wTs + 245760, 256, 128, 98304);
        transpose_kernel<<<384, 256>>>(PP[10], wTs + 344064, 128, 256, 98304);
    }

    // joint embedding
    embed_kernel<<<182784, 256>>>(poses, emb_w, emb_b, A, 46792704);

    // stage 1: 21504 graphs of 17 nodes
    const float* f1 = run_gps<17, 8>(PPj, A, Bb, Cc, 21504,
                                     1.f / 365568.f, wT, acc, fold, foldId);

    // pool joints -> stage2 input [1792, 12, 128]
    pool1_kernel<<<10752, 256>>>(A, f1, A2, 2752512);

    // stage 2: 1792 graphs of 12 nodes
    const float* f2 = run_gps<12, 2>(PPi, A2, B2, C2, 1792,
                                     1.f / 21504.f, wT + 442368, acc + 2304,
                                     fold + 2304, foldId);

    // final pool + classifier -> [256, 8]
    pool2_cls_kernel<<<256, 128>>>(A2, f2, cls_w, cls_b, (float*)d_out);
}